// round 15
// baseline (speedup 1.0000x reference)
#include <cuda_runtime.h>
#include <cuda_bf16.h>
#include <mma.h>
#include <math.h>
#include <stdint.h>

using namespace nvcuda;

#define NSAMP 8192
#define MODES 32
#define KDIM  64          // 32 cos + 32 sin rows (freq-major)
#define BATCH 32
#define CH    64
#define ROWS  2048        // BATCH*CH
#define LSEG  20
#define MCHEB 8
#define NNODES 160        // LSEG*MCHEB
#define KSPLIT 32         // forward k-splits (256 k per CTA)
#define BK     64
#define NCHUNK 4          // 256 / 64
#define LDA    72         // forward smem pad (bf16 elems)
#define LDIA   72         // inverse A pad
#define LDIB   136        // inverse B pad

typedef unsigned long long ull;

// ---------------- device scratch (no allocations allowed) ----------------
__device__ __nv_bfloat16  g_Fhi[KDIM*NSAMP];       // [freq][n] bf16 hi
__device__ __nv_bfloat16  g_Flo[KDIM*NSAMP];       // [freq][n] bf16 lo
__device__ float          g_Ar[NNODES*MODES];
__device__ float          g_Ai[NNODES*MODES];
__device__ int            g_nodeL[NNODES];
__device__ float          g_nodeWL[NNODES];
__device__ float          g_nodeWR[NNODES];
__device__ float          g_sfor[ROWS*KDIM];
__device__ float          g_norm[ROWS*MODES];
__device__ float          g_gate[BATCH*CH*MODES];
__device__ __nv_bfloat16  g_coefHi[ROWS*KDIM];     // irfft coefficients hi
__device__ __nv_bfloat16  g_coefLo[ROWS*KDIM];     // irfft coefficients lo
__device__ float          g_w1Tr[MODES*CH*CH];
__device__ float          g_w1Ti[MODES*CH*CH];

// ---------------- setup: DFT twiddle tables + zero g_sfor -----------------
__global__ void k_setup_F() {
    int idx = blockIdx.x * blockDim.x + threadIdx.x;
    if (idx < ROWS * KDIM) g_sfor[idx] = 0.0f;            // fold in zeroing
    if (idx >= KDIM * NSAMP) return;
    int k = idx >> 13, n = idx & (NSAMP - 1);
    int kf = k & 31;
    int m = (n * kf) & (NSAMP - 1);                       // exact phase mod 2pi
    float xm = (float)m * (1.0f / 4096.0f);               // exact (pow2 denom)
    float v = (k < MODES) ? cospif(xm) : sinpif(xm);
    __nv_bfloat16 hi = __float2bfloat16_rn(v);
    g_Fhi[idx] = hi;
    g_Flo[idx] = __float2bfloat16_rn(v - __bfloat162float(hi));
}

// ---------------- setup: CFT quadrature (one block, mostly float) ---------
__global__ void k_setup_WA() {
    __shared__ float sWr[MCHEB * MODES], sWi[MCHEB * MODES];
    const int tid = threadIdx.x;                          // 256 threads
    const float PIf = 3.14159265358979323846f;
    {
        int kc = tid >> 5, f = tid & 31;
        float Wr = 0.0f, Wi = 0.0f;
        for (int mp = 0; mp < MCHEB; mp++) {
            float chebp = -cosf((2.0f * mp + 1.0f) * PIf / (2.0f * MCHEB));
            float Tkm = cosf((float)kc * acosf(chebp));
            float ang = chebp * (float)f * (PIf / (float)LSEG);
            Wr += Tkm * cosf(ang);
            Wi += Tkm * (-sinf(ang));
        }
        float s = 1.0f / (2.0f * LSEG);
        sWr[tid] = Wr * s;
        sWi[tid] = Wi * s;
    }
    if (tid < NNODES) {
        int l = tid / MCHEB, m = tid % MCHEB;
        double cheb = -cos((2.0 * m + 1.0) * 3.14159265358979323846 / (2.0 * MCHEB));
        double tseg = (double)l / LSEG + (1.0 / (2.0 * LSEG)) * (cheb + 1.0);
        int right = (int)ceil(tseg * (double)(NSAMP - 1));
        if (right < 1) right = 1;
        if (right > NSAMP - 1) right = NSAMP - 1;
        int left = right - 1;
        double wr = tseg * (double)(NSAMP - 1) - (double)left;
        g_nodeL[tid]  = left;
        g_nodeWR[tid] = (float)wr;
        g_nodeWL[tid] = (float)(1.0 - wr);
    }
    __syncthreads();
    for (int idx = tid; idx < NNODES * MODES; idx += 256) {
        int j = idx >> 5, f = idx & 31;
        int l = j >> 3, mc = j & 7;
        float Wr = sWr[mc * MODES + f], Wi = sWi[mc * MODES + f];
        int r = (l * f) % LSEG;
        float ph = (float)r * (2.0f / (float)LSEG);
        float cphi = cospif(ph), sphi = sinpif(ph);
        g_Ar[idx] =  Wr * cphi + Wi * sphi;
        g_Ai[idx] = -Wr * sphi + Wi * cphi;
    }
}

// ---------------- setup: transpose w1 to f-major (tiled, coalesced) -------
__global__ void k_transpose_w1(const float* __restrict__ wr, const float* __restrict__ wi) {
    __shared__ float tr[32][33], ti[32][33];
    const int rbase = blockIdx.x * 32;
    const int t = threadIdx.x;            // 256
    {
        int f = t & 31, rr = t >> 5;
#pragma unroll
        for (int s = 0; s < 4; s++) {
            int r = rr + s * 8;
            tr[r][f] = __ldg(&wr[(size_t)(rbase + r) * MODES + f]);
            ti[r][f] = __ldg(&wi[(size_t)(rbase + r) * MODES + f]);
        }
    }
    __syncthreads();
    {
        int r = t & 31, ff = t >> 5;
#pragma unroll
        for (int s = 0; s < 4; s++) {
            int f = ff + s * 8;
            g_w1Tr[(size_t)f * (CH * CH) + rbase + r] = tr[r][f];
            g_w1Ti[(size_t)f * (CH * CH) + rbase + r] = ti[r][f];
        }
    }
}

// ---------------- forward GEMM via WMMA split-bf16, BK=64, atomic out -----
// grid (16 row-tiles, 32 k-splits). 256 threads = 8 warps, 3 CTAs/SM.
__global__ __launch_bounds__(256, 3) void k_forward_wmma(const float* __restrict__ x) {
    __shared__ __align__(32) unsigned char smem_raw[55296];
    __nv_bfloat16 (*sAhi)[LDA] = (__nv_bfloat16(*)[LDA])(smem_raw);
    __nv_bfloat16 (*sAlo)[LDA] = (__nv_bfloat16(*)[LDA])(smem_raw + 18432);
    __nv_bfloat16 (*sBhi)[LDA] = (__nv_bfloat16(*)[LDA])(smem_raw + 36864);
    __nv_bfloat16 (*sBlo)[LDA] = (__nv_bfloat16(*)[LDA])(smem_raw + 46080);
    float* stage = (float*)smem_raw;                      // 32KB alias, post-loop
    const int tid = threadIdx.x, wid = tid >> 5;
    const int m0 = blockIdx.x * 128;
    const int kbase = blockIdx.y * (NSAMP / KSPLIT);      // 256-wide window

    wmma::fragment<wmma::accumulator, 16, 16, 16, float> acc[4];
#pragma unroll
    for (int c = 0; c < 4; c++) wmma::fill_fragment(acc[c], 0.0f);

    for (int ch = 0; ch < NCHUNK; ch++) {
        const int kc = kbase + ch * BK;
        __syncthreads();
        // ---- A: 128 rows x 64 k fp32 -> bf16 hi/lo (8 LDG.128/thread) ----
        {
            int row = tid >> 3, kq = (tid & 7) * 4;
#pragma unroll
            for (int p = 0; p < 4; p++) {
#pragma unroll
                for (int hh = 0; hh < 2; hh++) {
                    int r = row + p * 32, k = kq + hh * 32;
                    float4 f4 = *(const float4*)&x[(size_t)(m0 + r) * NSAMP + kc + k];
                    uint32_t h01, h23, l01, l23;
                    asm("cvt.rn.bf16x2.f32 %0, %1, %2;" : "=r"(h01) : "f"(f4.y), "f"(f4.x));
                    asm("cvt.rn.bf16x2.f32 %0, %1, %2;" : "=r"(h23) : "f"(f4.w), "f"(f4.z));
                    float hx = __uint_as_float(h01 << 16);
                    float hy = __uint_as_float(h01 & 0xFFFF0000u);
                    float hz = __uint_as_float(h23 << 16);
                    float hw = __uint_as_float(h23 & 0xFFFF0000u);
                    asm("cvt.rn.bf16x2.f32 %0, %1, %2;" : "=r"(l01) : "f"(f4.y - hy), "f"(f4.x - hx));
                    asm("cvt.rn.bf16x2.f32 %0, %1, %2;" : "=r"(l23) : "f"(f4.w - hw), "f"(f4.z - hz));
                    *(uint2*)&sAhi[r][k] = make_uint2(h01, h23);
                    *(uint2*)&sAlo[r][k] = make_uint2(l01, l23);
                }
            }
        }
        // ---- B: 64 freq x 64 k bf16, straight copy ----
        {
            int f = tid >> 2, kq = (tid & 3) * 8;
            *(uint4*)&sBhi[f][kq]      = *(const uint4*)&g_Fhi[(size_t)f * NSAMP + kc + kq];
            *(uint4*)&sBhi[f][kq + 32] = *(const uint4*)&g_Fhi[(size_t)f * NSAMP + kc + kq + 32];
            *(uint4*)&sBlo[f][kq]      = *(const uint4*)&g_Flo[(size_t)f * NSAMP + kc + kq];
            *(uint4*)&sBlo[f][kq + 32] = *(const uint4*)&g_Flo[(size_t)f * NSAMP + kc + kq + 32];
        }
        __syncthreads();
#pragma unroll
        for (int ks = 0; ks < BK / 16; ks++) {
            wmma::fragment<wmma::matrix_a, 16, 16, 16, __nv_bfloat16, wmma::row_major> ahi, alo;
            wmma::load_matrix_sync(ahi, &sAhi[wid * 16][ks * 16], LDA);
            wmma::load_matrix_sync(alo, &sAlo[wid * 16][ks * 16], LDA);
#pragma unroll
            for (int c = 0; c < 4; c++) {
                wmma::fragment<wmma::matrix_b, 16, 16, 16, __nv_bfloat16, wmma::col_major> bhi, blo;
                wmma::load_matrix_sync(bhi, &sBhi[c * 16][ks * 16], LDA);
                wmma::load_matrix_sync(blo, &sBlo[c * 16][ks * 16], LDA);
                wmma::mma_sync(acc[c], ahi, bhi, acc[c]);
                wmma::mma_sync(acc[c], ahi, blo, acc[c]);
                wmma::mma_sync(acc[c], alo, bhi, acc[c]);
            }
        }
    }
    // ---- stage fp32 results in smem, then atomicAdd into g_sfor ----
    __syncthreads();
#pragma unroll
    for (int c = 0; c < 4; c++)
        wmma::store_matrix_sync(&stage[(size_t)(wid * 16) * KDIM + c * 16],
                                acc[c], KDIM, wmma::mem_row_major);
    __syncthreads();
    {
        // 128x64 elements, 256 threads -> 32 each (float4 granularity: 8 x float4)
        int base = tid * 8;                     // float4 index
#pragma unroll
        for (int q = 0; q < 8; q++) {
            int e4 = base + q;                  // 0..2047
            int r = e4 >> 4, c0 = (e4 & 15) * 4;
            float4 v = *(float4*)&stage[(size_t)r * KDIM + c0];
            float* dst = &g_sfor[(size_t)(m0 + r) * KDIM + c0];
            atomicAdd(dst + 0, v.x);
            atomicAdd(dst + 1, v.y);
            atomicAdd(dst + 2, v.z);
            atomicAdd(dst + 3, v.w);
        }
    }
}

// ---------------- CFT magnitude + fused LayerNorm (256 thr) ---------------
__global__ void k_mag(const float* __restrict__ x,
                      const float* __restrict__ gamma,
                      const float* __restrict__ beta) {
    __shared__ float v[NNODES];
    __shared__ float pre[8][MODES], pim[8][MODES];
    const int row = blockIdx.x;
    const int tid = threadIdx.x;
    if (tid < NNODES) {
        int l = g_nodeL[tid];
        v[tid] = g_nodeWL[tid] * x[(size_t)row * NSAMP + l]
               + g_nodeWR[tid] * x[(size_t)row * NSAMP + l + 1];
    }
    __syncthreads();
    {
        const int w = tid >> 5, f = tid & 31;
        float re = 0.0f, im = 0.0f;
        const int j0 = w * 20;
#pragma unroll
        for (int j = 0; j < 20; j++) {
            float vv = v[j0 + j];
            re = fmaf(vv, __ldg(&g_Ar[(j0 + j) * MODES + f]), re);
            im = fmaf(vv, __ldg(&g_Ai[(j0 + j) * MODES + f]), im);
        }
        pre[w][f] = re; pim[w][f] = im;
    }
    __syncthreads();
    if (tid < MODES) {
        float re = 0.0f, im = 0.0f;
#pragma unroll
        for (int w = 0; w < 8; w++) { re += pre[w][tid]; im += pim[w][tid]; }
        float mag = sqrtf(re * re + im * im);
        float mu = mag;
#pragma unroll
        for (int s = 16; s > 0; s >>= 1) mu += __shfl_xor_sync(0xffffffffu, mu, s);
        mu *= (1.0f / MODES);
        float d = mag - mu;
        float var = d * d;
#pragma unroll
        for (int s = 16; s > 0; s >>= 1) var += __shfl_xor_sync(0xffffffffu, var, s);
        var *= (1.0f / MODES);
        float inv = rsqrtf(var + 1e-5f);
        g_norm[(size_t)row * MODES + tid] = d * inv * gamma[tid] + beta[tid];
    }
}

// ---------------- 1x1 conv gate: grid (BATCH, 4) -------------------------
__global__ void k_gate(const float* __restrict__ gate_w) {
    __shared__ float sg[CH * MODES];
    const int b = blockIdx.x;
    const int o0 = blockIdx.y * 16;
    const int tid = threadIdx.x;
    for (int e = tid; e < CH * MODES; e += blockDim.x)
        sg[e] = g_norm[(size_t)b * CH * MODES + e];
    __syncthreads();
    for (int ee = tid; ee < 16 * MODES; ee += blockDim.x) {
        int o = o0 + (ee >> 5), f = ee & 31;
        float z = 0.0f;
#pragma unroll 8
        for (int i = 0; i < CH; i++)
            z = fmaf(__ldg(&gate_w[o * CH + i]), sg[i * MODES + f], z);
        g_gate[(size_t)b * CH * MODES + o * MODES + f] = 1.0f / (1.0f + expf(-z));
    }
}

// -------- per-(b, 4 freqs) 64x64 complex matvec; coef as bf16 hi/lo -------
__global__ void k_modes() {
    const int b = blockIdx.x;
    const int f0 = blockIdx.y * 4;
    const int tid = threadIdx.x;          // 256
    const int o = tid & 63, fi = tid >> 6;
    const int f = f0 + fi;
    __shared__ float gr[4][CH], gi[4][CH];
    {
        int i = o;
        float g = g_gate[((size_t)b * CH + i) * MODES + f];
        gr[fi][i] =  g_sfor[((size_t)b * CH + i) * KDIM + f] * g;
        gi[fi][i] = -g_sfor[((size_t)b * CH + i) * KDIM + MODES + f] * g;
    }
    __syncthreads();
    float orr = 0.0f, oii = 0.0f;
    const float* wr = &g_w1Tr[(size_t)f * CH * CH];
    const float* wi = &g_w1Ti[(size_t)f * CH * CH];
#pragma unroll 8
    for (int i = 0; i < CH; i++) {
        float a = gr[fi][i], c = gi[fi][i];
        float xr = wr[i * CH + o], xi = wi[i * CH + o];
        orr = fmaf(a, xr, orr); orr = fmaf(-c, xi, orr);
        oii = fmaf(a, xi, oii); oii = fmaf( c, xr, oii);
    }
    float sc = (f == 0) ? (1.0f / NSAMP) : (2.0f / NSAMP);
    int row = b * CH + o;
    float cr = sc * orr;
    float ci = (f == 0) ? 0.0f : (-sc * oii);   // imag of bin 0 ignored by hc2r
    __nv_bfloat16 h;
    h = __float2bfloat16_rn(cr);
    g_coefHi[(size_t)row * KDIM + f] = h;
    g_coefLo[(size_t)row * KDIM + f] = __float2bfloat16_rn(cr - __bfloat162float(h));
    h = __float2bfloat16_rn(ci);
    g_coefHi[(size_t)row * KDIM + MODES + f] = h;
    g_coefLo[(size_t)row * KDIM + MODES + f] = __float2bfloat16_rn(ci - __bfloat162float(h));
}

// ---------------- inverse via WMMA split-bf16, 128x128 tiles --------------
// out[2048x8192] = coef[2048x64] * F[64x8192].  grid (64, 16).
// Warp w: row tiles {(w&3)*2, (w&3)*2+1}, col tiles (w>>2)*4 .. +3.
__global__ __launch_bounds__(256, 2) void k_inverse_wmma(float* __restrict__ out) {
    __shared__ __align__(32) __nv_bfloat16 sA[2][128][LDIA];  // [hi/lo][row][k] 36.9KB
    __shared__ __align__(32) __nv_bfloat16 sB[2][64][LDIB];   // [hi/lo][freq][n] 34.8KB
    const int tid = threadIdx.x, w = tid >> 5;
    const int n0 = blockIdx.x * 128;
    const int r0 = blockIdx.y * 128;
    // load A: 2 parts x 128 rows x 64 k = 2048 uint4, 8 per thread
#pragma unroll
    for (int p = 0; p < 2; p++) {
        const __nv_bfloat16* src = p ? g_coefLo : g_coefHi;
#pragma unroll
        for (int q = 0; q < 4; q++) {
            int e4 = tid * 4 + q;                 // 0..1023
            int r = e4 >> 3, c = (e4 & 7) * 8;
            *(uint4*)&sA[p][r][c] = *(const uint4*)&src[(size_t)(r0 + r) * KDIM + c];
        }
    }
    // load B: 2 parts x 64 freq x 128 n = 2048 uint4, 8 per thread
#pragma unroll
    for (int p = 0; p < 2; p++) {
        const __nv_bfloat16* src = p ? g_Flo : g_Fhi;
#pragma unroll
        for (int q = 0; q < 4; q++) {
            int e4 = tid * 4 + q;                 // 0..1023
            int r = e4 >> 4, c = (e4 & 15) * 8;
            *(uint4*)&sB[p][r][c] = *(const uint4*)&src[(size_t)r * NSAMP + n0 + c];
        }
    }
    __syncthreads();
    const int wm = (w & 3) * 2, wn = (w >> 2) * 4;
    wmma::fragment<wmma::accumulator, 16, 16, 16, float> acc[2][4];
#pragma unroll
    for (int i = 0; i < 2; i++)
#pragma unroll
        for (int j = 0; j < 4; j++) wmma::fill_fragment(acc[i][j], 0.0f);
#pragma unroll
    for (int kt = 0; kt < 4; kt++) {
        wmma::fragment<wmma::matrix_a, 16, 16, 16, __nv_bfloat16, wmma::row_major> ahi[2], alo[2];
#pragma unroll
        for (int i = 0; i < 2; i++) {
            wmma::load_matrix_sync(ahi[i], &sA[0][(wm + i) * 16][kt * 16], LDIA);
            wmma::load_matrix_sync(alo[i], &sA[1][(wm + i) * 16][kt * 16], LDIA);
        }
#pragma unroll
        for (int j = 0; j < 4; j++) {
            int nc = (wn + j) * 16;
            wmma::fragment<wmma::matrix_b, 16, 16, 16, __nv_bfloat16, wmma::row_major> bhi, blo;
            wmma::load_matrix_sync(bhi, &sB[0][kt * 16][nc], LDIB);
            wmma::load_matrix_sync(blo, &sB[1][kt * 16][nc], LDIB);
#pragma unroll
            for (int i = 0; i < 2; i++) {
                wmma::mma_sync(acc[i][j], ahi[i], bhi, acc[i][j]);
                wmma::mma_sync(acc[i][j], ahi[i], blo, acc[i][j]);
                wmma::mma_sync(acc[i][j], alo[i], bhi, acc[i][j]);
            }
        }
    }
#pragma unroll
    for (int i = 0; i < 2; i++)
#pragma unroll
        for (int j = 0; j < 4; j++)
            wmma::store_matrix_sync(
                &out[(size_t)(r0 + (wm + i) * 16) * NSAMP + n0 + (wn + j) * 16],
                acc[i][j], NSAMP, wmma::mem_row_major);
}

// ---------------- launch ----------------
extern "C" void kernel_launch(void* const* d_in, const int* in_sizes, int n_in,
                              void* d_out, int out_size) {
    const float* x     = (const float*)d_in[0];
    const float* w1r   = (const float*)d_in[1];
    const float* w1i   = (const float*)d_in[2];
    const float* gw    = (const float*)d_in[3];
    const float* gamma = (const float*)d_in[4];
    const float* beta  = (const float*)d_in[5];
    float* out = (float*)d_out;

    k_setup_F<<<KDIM * NSAMP / 256, 256>>>();
    k_setup_WA<<<1, 256>>>();
    k_transpose_w1<<<CH * CH / 32, 256>>>(w1r, w1i);
    k_forward_wmma<<<dim3(ROWS / 128, KSPLIT), 256>>>(x);
    k_mag<<<ROWS, 256>>>(x, gamma, beta);
    k_gate<<<dim3(BATCH, 4), 256>>>(gw);
    k_modes<<<dim3(BATCH, MODES / 4), 256>>>();
    k_inverse_wmma<<<dim3(NSAMP / 128, ROWS / 128), 256>>>(out);
}

// round 16
// speedup vs baseline: 1.1488x; 1.1488x over previous
#include <cuda_runtime.h>
#include <cuda_bf16.h>
#include <mma.h>
#include <math.h>
#include <stdint.h>

using namespace nvcuda;

#define NSAMP 8192
#define MODES 32
#define KDIM  64          // 32 cos + 32 sin rows (freq-major)
#define BATCH 32
#define CH    64
#define ROWS  2048        // BATCH*CH
#define LSEG  20
#define MCHEB 8
#define NNODES 160        // LSEG*MCHEB
#define KSPLIT 32         // forward k-splits (256 k per CTA)
#define NSLICE KSPLIT
#define BK     64
#define NCHUNK 4          // 256 / 64
#define LDA    72         // forward smem pad (bf16 elems)
#define LDIA   72         // inverse A pad
#define LDIB   136        // inverse B pad

typedef unsigned long long ull;

// ---------------- device scratch (no allocations allowed) ----------------
__device__ __nv_bfloat16  g_Fhi[KDIM*NSAMP];       // [freq][n] bf16 hi
__device__ __nv_bfloat16  g_Flo[KDIM*NSAMP];       // [freq][n] bf16 lo
__device__ float          g_part[NSLICE*ROWS*KDIM]; // forward partials (16MB)
__device__ float          g_Ar[NNODES*MODES];
__device__ float          g_Ai[NNODES*MODES];
__device__ int            g_nodeL[NNODES];
__device__ float          g_nodeWL[NNODES];
__device__ float          g_nodeWR[NNODES];
__device__ float          g_sfor[ROWS*KDIM];
__device__ float          g_norm[ROWS*MODES];
__device__ float          g_gate[BATCH*CH*MODES];
__device__ __nv_bfloat16  g_coefHi[ROWS*KDIM];     // irfft coefficients hi
__device__ __nv_bfloat16  g_coefLo[ROWS*KDIM];     // irfft coefficients lo
__device__ float          g_w1Tr[MODES*CH*CH];
__device__ float          g_w1Ti[MODES*CH*CH];

// ---------------- setup: DFT twiddle tables (bf16 hi/lo) ------------------
__global__ void k_setup_F() {
    int idx = blockIdx.x * blockDim.x + threadIdx.x;
    if (idx >= KDIM * NSAMP) return;
    int k = idx >> 13, n = idx & (NSAMP - 1);
    int kf = k & 31;
    int m = (n * kf) & (NSAMP - 1);                       // exact phase mod 2pi
    float xm = (float)m * (1.0f / 4096.0f);               // exact (pow2 denom)
    float v = (k < MODES) ? cospif(xm) : sinpif(xm);
    __nv_bfloat16 hi = __float2bfloat16_rn(v);
    g_Fhi[idx] = hi;
    g_Flo[idx] = __float2bfloat16_rn(v - __bfloat162float(hi));
}

// ---------------- setup: CFT quadrature (one block, mostly float) ---------
__global__ void k_setup_WA() {
    __shared__ float sWr[MCHEB * MODES], sWi[MCHEB * MODES];
    const int tid = threadIdx.x;                          // 256 threads
    const float PIf = 3.14159265358979323846f;
    {
        int kc = tid >> 5, f = tid & 31;
        float Wr = 0.0f, Wi = 0.0f;
        for (int mp = 0; mp < MCHEB; mp++) {
            float chebp = -cosf((2.0f * mp + 1.0f) * PIf / (2.0f * MCHEB));
            float Tkm = cosf((float)kc * acosf(chebp));
            float ang = chebp * (float)f * (PIf / (float)LSEG);
            Wr += Tkm * cosf(ang);
            Wi += Tkm * (-sinf(ang));
        }
        float s = 1.0f / (2.0f * LSEG);
        sWr[tid] = Wr * s;
        sWi[tid] = Wi * s;
    }
    if (tid < NNODES) {
        int l = tid / MCHEB, m = tid % MCHEB;
        double cheb = -cos((2.0 * m + 1.0) * 3.14159265358979323846 / (2.0 * MCHEB));
        double tseg = (double)l / LSEG + (1.0 / (2.0 * LSEG)) * (cheb + 1.0);
        int right = (int)ceil(tseg * (double)(NSAMP - 1));
        if (right < 1) right = 1;
        if (right > NSAMP - 1) right = NSAMP - 1;
        int left = right - 1;
        double wr = tseg * (double)(NSAMP - 1) - (double)left;
        g_nodeL[tid]  = left;
        g_nodeWR[tid] = (float)wr;
        g_nodeWL[tid] = (float)(1.0 - wr);
    }
    __syncthreads();
    for (int idx = tid; idx < NNODES * MODES; idx += 256) {
        int j = idx >> 5, f = idx & 31;
        int l = j >> 3, mc = j & 7;
        float Wr = sWr[mc * MODES + f], Wi = sWi[mc * MODES + f];
        int r = (l * f) % LSEG;
        float ph = (float)r * (2.0f / (float)LSEG);
        float cphi = cospif(ph), sphi = sinpif(ph);
        g_Ar[idx] =  Wr * cphi + Wi * sphi;
        g_Ai[idx] = -Wr * sphi + Wi * cphi;
    }
}

// ---------------- setup: transpose w1 to f-major (tiled, coalesced) -------
__global__ void k_transpose_w1(const float* __restrict__ wr, const float* __restrict__ wi) {
    __shared__ float tr[32][33], ti[32][33];
    const int rbase = blockIdx.x * 32;
    const int t = threadIdx.x;            // 256
    {
        int f = t & 31, rr = t >> 5;
#pragma unroll
        for (int s = 0; s < 4; s++) {
            int r = rr + s * 8;
            tr[r][f] = __ldg(&wr[(size_t)(rbase + r) * MODES + f]);
            ti[r][f] = __ldg(&wi[(size_t)(rbase + r) * MODES + f]);
        }
    }
    __syncthreads();
    {
        int r = t & 31, ff = t >> 5;
#pragma unroll
        for (int s = 0; s < 4; s++) {
            int f = ff + s * 8;
            g_w1Tr[(size_t)f * (CH * CH) + rbase + r] = tr[r][f];
            g_w1Ti[(size_t)f * (CH * CH) + rbase + r] = ti[r][f];
        }
    }
}

// ---------------- forward GEMM via WMMA split-bf16, BK=64 (R14) -----------
// grid (16 row-tiles, 32 k-splits). 256 threads = 8 warps, 3 CTAs/SM.
__global__ __launch_bounds__(256, 3) void k_forward_wmma(const float* __restrict__ x) {
    __shared__ __align__(32) __nv_bfloat16 sAhi[128][LDA];   // [row][k], 18KB
    __shared__ __align__(32) __nv_bfloat16 sAlo[128][LDA];
    __shared__ __align__(32) __nv_bfloat16 sBhi[KDIM][LDA];  // [freq][k], 9KB
    __shared__ __align__(32) __nv_bfloat16 sBlo[KDIM][LDA];
    const int tid = threadIdx.x, wid = tid >> 5;
    const int m0 = blockIdx.x * 128;
    const int kbase = blockIdx.y * (NSAMP / KSPLIT);   // 256-wide window

    wmma::fragment<wmma::accumulator, 16, 16, 16, float> acc[4];
#pragma unroll
    for (int c = 0; c < 4; c++) wmma::fill_fragment(acc[c], 0.0f);

    for (int ch = 0; ch < NCHUNK; ch++) {
        const int kc = kbase + ch * BK;
        __syncthreads();
        // ---- A: 128 rows x 64 k fp32 -> bf16 hi/lo (8 LDG.128/thread) ----
        {
            int row = tid >> 3, kq = (tid & 7) * 4;   // row 0..31, kq 0..28
#pragma unroll
            for (int p = 0; p < 4; p++) {
#pragma unroll
                for (int hh = 0; hh < 2; hh++) {
                    int r = row + p * 32, k = kq + hh * 32;
                    float4 f4 = *(const float4*)&x[(size_t)(m0 + r) * NSAMP + kc + k];
                    uint32_t h01, h23, l01, l23;
                    asm("cvt.rn.bf16x2.f32 %0, %1, %2;" : "=r"(h01) : "f"(f4.y), "f"(f4.x));
                    asm("cvt.rn.bf16x2.f32 %0, %1, %2;" : "=r"(h23) : "f"(f4.w), "f"(f4.z));
                    float hx = __uint_as_float(h01 << 16);
                    float hy = __uint_as_float(h01 & 0xFFFF0000u);
                    float hz = __uint_as_float(h23 << 16);
                    float hw = __uint_as_float(h23 & 0xFFFF0000u);
                    asm("cvt.rn.bf16x2.f32 %0, %1, %2;" : "=r"(l01) : "f"(f4.y - hy), "f"(f4.x - hx));
                    asm("cvt.rn.bf16x2.f32 %0, %1, %2;" : "=r"(l23) : "f"(f4.w - hw), "f"(f4.z - hz));
                    *(uint2*)&sAhi[r][k] = make_uint2(h01, h23);
                    *(uint2*)&sAlo[r][k] = make_uint2(l01, l23);
                }
            }
        }
        // ---- B: 64 freq x 64 k bf16, straight copy ----
        {
            int f = tid >> 2, kq = (tid & 3) * 8;
            *(uint4*)&sBhi[f][kq]      = *(const uint4*)&g_Fhi[(size_t)f * NSAMP + kc + kq];
            *(uint4*)&sBhi[f][kq + 32] = *(const uint4*)&g_Fhi[(size_t)f * NSAMP + kc + kq + 32];
            *(uint4*)&sBlo[f][kq]      = *(const uint4*)&g_Flo[(size_t)f * NSAMP + kc + kq];
            *(uint4*)&sBlo[f][kq + 32] = *(const uint4*)&g_Flo[(size_t)f * NSAMP + kc + kq + 32];
        }
        __syncthreads();
#pragma unroll
        for (int ks = 0; ks < BK / 16; ks++) {
            wmma::fragment<wmma::matrix_a, 16, 16, 16, __nv_bfloat16, wmma::row_major> ahi, alo;
            wmma::load_matrix_sync(ahi, &sAhi[wid * 16][ks * 16], LDA);
            wmma::load_matrix_sync(alo, &sAlo[wid * 16][ks * 16], LDA);
#pragma unroll
            for (int c = 0; c < 4; c++) {
                wmma::fragment<wmma::matrix_b, 16, 16, 16, __nv_bfloat16, wmma::col_major> bhi, blo;
                wmma::load_matrix_sync(bhi, &sBhi[c * 16][ks * 16], LDA);
                wmma::load_matrix_sync(blo, &sBlo[c * 16][ks * 16], LDA);
                wmma::mma_sync(acc[c], ahi, bhi, acc[c]);
                wmma::mma_sync(acc[c], ahi, blo, acc[c]);
                wmma::mma_sync(acc[c], alo, bhi, acc[c]);
            }
        }
    }
    float* dst = &g_part[(size_t)blockIdx.y * ROWS * KDIM + (size_t)(m0 + wid * 16) * KDIM];
#pragma unroll
    for (int c = 0; c < 4; c++)
        wmma::store_matrix_sync(dst + c * 16, acc[c], KDIM, wmma::mem_row_major);
}

// ---- CFT magnitude + LayerNorm + fused slice-reduction (one blk/row) ----
__global__ void k_mag(const float* __restrict__ x,
                      const float* __restrict__ gamma,
                      const float* __restrict__ beta) {
    __shared__ float v[NNODES];
    __shared__ float pre[8][MODES], pim[8][MODES];
    __shared__ float sred[4][KDIM];
    const int row = blockIdx.x;
    const int tid = threadIdx.x;
    // slice reduction: 256 threads, col = tid&63, quarter = tid>>6 (8 slices each)
    {
        int col = tid & 63, q = tid >> 6;
        float s0 = 0.f, s1 = 0.f;
#pragma unroll
        for (int p = 0; p < 4; p++) {
            s0 += g_part[((size_t)(q * 8 + 2 * p)     * ROWS + row) * KDIM + col];
            s1 += g_part[((size_t)(q * 8 + 2 * p + 1) * ROWS + row) * KDIM + col];
        }
        sred[q][col] = s0 + s1;
    }
    if (tid < NNODES) {
        int l = g_nodeL[tid];
        v[tid] = g_nodeWL[tid] * x[(size_t)row * NSAMP + l]
               + g_nodeWR[tid] * x[(size_t)row * NSAMP + l + 1];
    }
    __syncthreads();
    if (tid < KDIM)
        g_sfor[(size_t)row * KDIM + tid] =
            sred[0][tid] + sred[1][tid] + sred[2][tid] + sred[3][tid];
    {
        const int w = tid >> 5, f = tid & 31;
        float re = 0.0f, im = 0.0f;
        const int j0 = w * 20;
#pragma unroll
        for (int j = 0; j < 20; j++) {
            float vv = v[j0 + j];
            re = fmaf(vv, __ldg(&g_Ar[(j0 + j) * MODES + f]), re);
            im = fmaf(vv, __ldg(&g_Ai[(j0 + j) * MODES + f]), im);
        }
        pre[w][f] = re; pim[w][f] = im;
    }
    __syncthreads();
    if (tid < MODES) {
        float re = 0.0f, im = 0.0f;
#pragma unroll
        for (int w = 0; w < 8; w++) { re += pre[w][tid]; im += pim[w][tid]; }
        float mag = sqrtf(re * re + im * im);
        float mu = mag;
#pragma unroll
        for (int s = 16; s > 0; s >>= 1) mu += __shfl_xor_sync(0xffffffffu, mu, s);
        mu *= (1.0f / MODES);
        float d = mag - mu;
        float var = d * d;
#pragma unroll
        for (int s = 16; s > 0; s >>= 1) var += __shfl_xor_sync(0xffffffffu, var, s);
        var *= (1.0f / MODES);
        float inv = rsqrtf(var + 1e-5f);
        g_norm[(size_t)row * MODES + tid] = d * inv * gamma[tid] + beta[tid];
    }
}

// ---------------- 1x1 conv gate: grid (BATCH, 4) -------------------------
__global__ void k_gate(const float* __restrict__ gate_w) {
    __shared__ float sg[CH * MODES];
    const int b = blockIdx.x;
    const int o0 = blockIdx.y * 16;
    const int tid = threadIdx.x;
    for (int e = tid; e < CH * MODES; e += blockDim.x)
        sg[e] = g_norm[(size_t)b * CH * MODES + e];
    __syncthreads();
    for (int ee = tid; ee < 16 * MODES; ee += blockDim.x) {
        int o = o0 + (ee >> 5), f = ee & 31;
        float z = 0.0f;
#pragma unroll 8
        for (int i = 0; i < CH; i++)
            z = fmaf(__ldg(&gate_w[o * CH + i]), sg[i * MODES + f], z);
        g_gate[(size_t)b * CH * MODES + o * MODES + f] = 1.0f / (1.0f + expf(-z));
    }
}

// -------- per-(b, 4 freqs) 64x64 complex matvec; coef as bf16 hi/lo -------
__global__ void k_modes() {
    const int b = blockIdx.x;
    const int f0 = blockIdx.y * 4;
    const int tid = threadIdx.x;          // 256
    const int o = tid & 63, fi = tid >> 6;
    const int f = f0 + fi;
    __shared__ float gr[4][CH], gi[4][CH];
    {
        int i = o;
        float g = g_gate[((size_t)b * CH + i) * MODES + f];
        gr[fi][i] =  g_sfor[((size_t)b * CH + i) * KDIM + f] * g;
        gi[fi][i] = -g_sfor[((size_t)b * CH + i) * KDIM + MODES + f] * g;
    }
    __syncthreads();
    float orr = 0.0f, oii = 0.0f;
    const float* wr = &g_w1Tr[(size_t)f * CH * CH];
    const float* wi = &g_w1Ti[(size_t)f * CH * CH];
#pragma unroll 8
    for (int i = 0; i < CH; i++) {
        float a = gr[fi][i], c = gi[fi][i];
        float xr = wr[i * CH + o], xi = wi[i * CH + o];
        orr = fmaf(a, xr, orr); orr = fmaf(-c, xi, orr);
        oii = fmaf(a, xi, oii); oii = fmaf( c, xr, oii);
    }
    float sc = (f == 0) ? (1.0f / NSAMP) : (2.0f / NSAMP);
    int row = b * CH + o;
    float cr = sc * orr;
    float ci = (f == 0) ? 0.0f : (-sc * oii);   // imag of bin 0 ignored by hc2r
    __nv_bfloat16 h;
    h = __float2bfloat16_rn(cr);
    g_coefHi[(size_t)row * KDIM + f] = h;
    g_coefLo[(size_t)row * KDIM + f] = __float2bfloat16_rn(cr - __bfloat162float(h));
    h = __float2bfloat16_rn(ci);
    g_coefHi[(size_t)row * KDIM + MODES + f] = h;
    g_coefLo[(size_t)row * KDIM + MODES + f] = __float2bfloat16_rn(ci - __bfloat162float(h));
}

// ---------------- inverse via WMMA split-bf16, 128x128 tiles (R15) --------
// out[2048x8192] = coef[2048x64] * F[64x8192].  grid (64, 16).
__global__ __launch_bounds__(256, 2) void k_inverse_wmma(float* __restrict__ out) {
    __shared__ __align__(32) __nv_bfloat16 sA[2][128][LDIA];  // [hi/lo][row][k] 36.9KB
    __shared__ __align__(32) __nv_bfloat16 sB[2][64][LDIB];   // [hi/lo][freq][n] 34.8KB
    const int tid = threadIdx.x, w = tid >> 5;
    const int n0 = blockIdx.x * 128;
    const int r0 = blockIdx.y * 128;
#pragma unroll
    for (int p = 0; p < 2; p++) {
        const __nv_bfloat16* src = p ? g_coefLo : g_coefHi;
#pragma unroll
        for (int q = 0; q < 4; q++) {
            int e4 = tid * 4 + q;                 // 0..1023
            int r = e4 >> 3, c = (e4 & 7) * 8;
            *(uint4*)&sA[p][r][c] = *(const uint4*)&src[(size_t)(r0 + r) * KDIM + c];
        }
    }
#pragma unroll
    for (int p = 0; p < 2; p++) {
        const __nv_bfloat16* src = p ? g_Flo : g_Fhi;
#pragma unroll
        for (int q = 0; q < 4; q++) {
            int e4 = tid * 4 + q;                 // 0..1023
            int r = e4 >> 4, c = (e4 & 15) * 8;
            *(uint4*)&sB[p][r][c] = *(const uint4*)&src[(size_t)r * NSAMP + n0 + c];
        }
    }
    __syncthreads();
    const int wm = (w & 3) * 2, wn = (w >> 2) * 4;
    wmma::fragment<wmma::accumulator, 16, 16, 16, float> acc[2][4];
#pragma unroll
    for (int i = 0; i < 2; i++)
#pragma unroll
        for (int j = 0; j < 4; j++) wmma::fill_fragment(acc[i][j], 0.0f);
#pragma unroll
    for (int kt = 0; kt < 4; kt++) {
        wmma::fragment<wmma::matrix_a, 16, 16, 16, __nv_bfloat16, wmma::row_major> ahi[2], alo[2];
#pragma unroll
        for (int i = 0; i < 2; i++) {
            wmma::load_matrix_sync(ahi[i], &sA[0][(wm + i) * 16][kt * 16], LDIA);
            wmma::load_matrix_sync(alo[i], &sA[1][(wm + i) * 16][kt * 16], LDIA);
        }
#pragma unroll
        for (int j = 0; j < 4; j++) {
            int nc = (wn + j) * 16;
            wmma::fragment<wmma::matrix_b, 16, 16, 16, __nv_bfloat16, wmma::row_major> bhi, blo;
            wmma::load_matrix_sync(bhi, &sB[0][kt * 16][nc], LDIB);
            wmma::load_matrix_sync(blo, &sB[1][kt * 16][nc], LDIB);
#pragma unroll
            for (int i = 0; i < 2; i++) {
                wmma::mma_sync(acc[i][j], ahi[i], bhi, acc[i][j]);
                wmma::mma_sync(acc[i][j], ahi[i], blo, acc[i][j]);
                wmma::mma_sync(acc[i][j], alo[i], bhi, acc[i][j]);
            }
        }
    }
#pragma unroll
    for (int i = 0; i < 2; i++)
#pragma unroll
        for (int j = 0; j < 4; j++)
            wmma::store_matrix_sync(
                &out[(size_t)(r0 + (wm + i) * 16) * NSAMP + n0 + (wn + j) * 16],
                acc[i][j], NSAMP, wmma::mem_row_major);
}

// ---------------- launch ----------------
extern "C" void kernel_launch(void* const* d_in, const int* in_sizes, int n_in,
                              void* d_out, int out_size) {
    const float* x     = (const float*)d_in[0];
    const float* w1r   = (const float*)d_in[1];
    const float* w1i   = (const float*)d_in[2];
    const float* gw    = (const float*)d_in[3];
    const float* gamma = (const float*)d_in[4];
    const float* beta  = (const float*)d_in[5];
    float* out = (float*)d_out;

    k_setup_F<<<KDIM * NSAMP / 256, 256>>>();
    k_setup_WA<<<1, 256>>>();
    k_transpose_w1<<<CH * CH / 32, 256>>>(w1r, w1i);
    k_forward_wmma<<<dim3(ROWS / 128, KSPLIT), 256>>>(x);
    k_mag<<<ROWS, 256>>>(x, gamma, beta);
    k_gate<<<dim3(BATCH, 4), 256>>>(gw);
    k_modes<<<dim3(BATCH, MODES / 4), 256>>>();
    k_inverse_wmma<<<dim3(NSAMP / 128, ROWS / 128), 256>>>(out);
}

// round 17
// speedup vs baseline: 1.1910x; 1.0368x over previous
#include <cuda_runtime.h>
#include <cuda_bf16.h>
#include <mma.h>
#include <math.h>
#include <stdint.h>

using namespace nvcuda;

#define NSAMP 8192
#define MODES 32
#define KDIM  64          // 32 cos + 32 sin rows (freq-major)
#define BATCH 32
#define CH    64
#define ROWS  2048        // BATCH*CH
#define LSEG  20
#define MCHEB 8
#define NNODES 160        // LSEG*MCHEB
#define KSPLIT 32         // forward k-splits (256 k per CTA)
#define NSLICE KSPLIT
#define BK     64
#define NCHUNK 4          // 256 / 64
#define LDA    72         // forward smem pad (bf16 elems)
#define LDIA   72         // inverse A pad
#define LDIB   136        // inverse B pad

typedef unsigned long long ull;

// ---------------- device scratch (no allocations allowed) ----------------
__device__ __nv_bfloat16  g_Fhi[KDIM*NSAMP];       // [freq][n] bf16 hi
__device__ __nv_bfloat16  g_Flo[KDIM*NSAMP];       // [freq][n] bf16 lo
__device__ float          g_part[NSLICE*ROWS*KDIM]; // forward partials (16MB)
__device__ float          g_Ar[NNODES*MODES];
__device__ float          g_Ai[NNODES*MODES];
__device__ int            g_nodeL[NNODES];
__device__ float          g_nodeWL[NNODES];
__device__ float          g_nodeWR[NNODES];
__device__ float          g_sfor[ROWS*KDIM];
__device__ float          g_norm[ROWS*MODES];
__device__ float          g_gate[BATCH*CH*MODES];
__device__ __nv_bfloat16  g_coefHi[ROWS*KDIM];     // irfft coefficients hi
__device__ __nv_bfloat16  g_coefLo[ROWS*KDIM];     // irfft coefficients lo
__device__ float          g_w1Tr[MODES*CH*CH];
__device__ float          g_w1Ti[MODES*CH*CH];

// -------- fused setup: F tables + w1 transpose + CFT quadrature -----------
// grid 2177: blocks 0..2047 F-table, 2048..2175 w1 transpose, 2176 quadrature
__global__ void k_setup_all(const float* __restrict__ wr, const float* __restrict__ wi) {
    const int bx = blockIdx.x;
    const int tid = threadIdx.x;
    if (bx < 2048) {
        int idx = bx * 256 + tid;
        int k = idx >> 13, n = idx & (NSAMP - 1);
        int kf = k & 31;
        int m = (n * kf) & (NSAMP - 1);                   // exact phase mod 2pi
        float xm = (float)m * (1.0f / 4096.0f);           // exact (pow2 denom)
        float v = (k < MODES) ? cospif(xm) : sinpif(xm);
        __nv_bfloat16 hi = __float2bfloat16_rn(v);
        g_Fhi[idx] = hi;
        g_Flo[idx] = __float2bfloat16_rn(v - __bfloat162float(hi));
    } else if (bx < 2176) {
        __shared__ float tr[32][33], ti[32][33];
        const int rbase = (bx - 2048) * 32;
        {
            int f = tid & 31, rr = tid >> 5;
#pragma unroll
            for (int s = 0; s < 4; s++) {
                int r = rr + s * 8;
                tr[r][f] = __ldg(&wr[(size_t)(rbase + r) * MODES + f]);
                ti[r][f] = __ldg(&wi[(size_t)(rbase + r) * MODES + f]);
            }
        }
        __syncthreads();
        {
            int r = tid & 31, ff = tid >> 5;
#pragma unroll
            for (int s = 0; s < 4; s++) {
                int f = ff + s * 8;
                g_w1Tr[(size_t)f * (CH * CH) + rbase + r] = tr[r][f];
                g_w1Ti[(size_t)f * (CH * CH) + rbase + r] = ti[r][f];
            }
        }
    } else {
        __shared__ float sWr[MCHEB * MODES], sWi[MCHEB * MODES];
        const float PIf = 3.14159265358979323846f;
        {
            int kc = tid >> 5, f = tid & 31;
            float Wr = 0.0f, Wi = 0.0f;
            for (int mp = 0; mp < MCHEB; mp++) {
                float chebp = -cosf((2.0f * mp + 1.0f) * PIf / (2.0f * MCHEB));
                float Tkm = cosf((float)kc * acosf(chebp));
                float ang = chebp * (float)f * (PIf / (float)LSEG);
                Wr += Tkm * cosf(ang);
                Wi += Tkm * (-sinf(ang));
            }
            float s = 1.0f / (2.0f * LSEG);
            sWr[tid] = Wr * s;
            sWi[tid] = Wi * s;
        }
        if (tid < NNODES) {
            int l = tid / MCHEB, m = tid % MCHEB;
            double cheb = -cos((2.0 * m + 1.0) * 3.14159265358979323846 / (2.0 * MCHEB));
            double tseg = (double)l / LSEG + (1.0 / (2.0 * LSEG)) * (cheb + 1.0);
            int right = (int)ceil(tseg * (double)(NSAMP - 1));
            if (right < 1) right = 1;
            if (right > NSAMP - 1) right = NSAMP - 1;
            int left = right - 1;
            double wrt = tseg * (double)(NSAMP - 1) - (double)left;
            g_nodeL[tid]  = left;
            g_nodeWR[tid] = (float)wrt;
            g_nodeWL[tid] = (float)(1.0 - wrt);
        }
        __syncthreads();
        for (int idx = tid; idx < NNODES * MODES; idx += 256) {
            int j = idx >> 5, f = idx & 31;
            int l = j >> 3, mc = j & 7;
            float Wr = sWr[mc * MODES + f], Wi = sWi[mc * MODES + f];
            int r = (l * f) % LSEG;
            float ph = (float)r * (2.0f / (float)LSEG);
            float cphi = cospif(ph), sphi = sinpif(ph);
            g_Ar[idx] =  Wr * cphi + Wi * sphi;
            g_Ai[idx] = -Wr * sphi + Wi * cphi;
        }
    }
}

// ---------------- forward GEMM via WMMA split-bf16, BK=64, reg-prefetch ---
// grid (16 row-tiles, 32 k-splits). 256 threads = 8 warps.
__global__ __launch_bounds__(256, 2) void k_forward_wmma(const float* __restrict__ x) {
    __shared__ __align__(32) __nv_bfloat16 sAhi[128][LDA];   // [row][k], 18KB
    __shared__ __align__(32) __nv_bfloat16 sAlo[128][LDA];
    __shared__ __align__(32) __nv_bfloat16 sBhi[KDIM][LDA];  // [freq][k], 9KB
    __shared__ __align__(32) __nv_bfloat16 sBlo[KDIM][LDA];
    const int tid = threadIdx.x, wid = tid >> 5;
    const int m0 = blockIdx.x * 128;
    const int kbase = blockIdx.y * (NSAMP / KSPLIT);   // 256-wide window
    const int arow = tid >> 3, akq = (tid & 7) * 4;

    float4 ra[8];
    auto loadA = [&](int kc) {
#pragma unroll
        for (int p = 0; p < 4; p++)
#pragma unroll
            for (int hh = 0; hh < 2; hh++)
                ra[p * 2 + hh] = *(const float4*)
                    &x[(size_t)(m0 + arow + p * 32) * NSAMP + kc + akq + hh * 32];
    };
    auto storeA = [&]() {
#pragma unroll
        for (int p = 0; p < 4; p++)
#pragma unroll
            for (int hh = 0; hh < 2; hh++) {
                int r = arow + p * 32, k = akq + hh * 32;
                float4 f4 = ra[p * 2 + hh];
                uint32_t h01, h23, l01, l23;
                asm("cvt.rn.bf16x2.f32 %0, %1, %2;" : "=r"(h01) : "f"(f4.y), "f"(f4.x));
                asm("cvt.rn.bf16x2.f32 %0, %1, %2;" : "=r"(h23) : "f"(f4.w), "f"(f4.z));
                float hx = __uint_as_float(h01 << 16);
                float hy = __uint_as_float(h01 & 0xFFFF0000u);
                float hz = __uint_as_float(h23 << 16);
                float hw = __uint_as_float(h23 & 0xFFFF0000u);
                asm("cvt.rn.bf16x2.f32 %0, %1, %2;" : "=r"(l01) : "f"(f4.y - hy), "f"(f4.x - hx));
                asm("cvt.rn.bf16x2.f32 %0, %1, %2;" : "=r"(l23) : "f"(f4.w - hw), "f"(f4.z - hz));
                *(uint2*)&sAhi[r][k] = make_uint2(h01, h23);
                *(uint2*)&sAlo[r][k] = make_uint2(l01, l23);
            }
    };

    wmma::fragment<wmma::accumulator, 16, 16, 16, float> acc[4];
#pragma unroll
    for (int c = 0; c < 4; c++) wmma::fill_fragment(acc[c], 0.0f);

    loadA(kbase);
    for (int ch = 0; ch < NCHUNK; ch++) {
        const int kc = kbase + ch * BK;
        __syncthreads();                 // prev mma done -> smem reusable
        storeA();                        // convert regs -> smem
        {
            int f = tid >> 2, kq = (tid & 3) * 8;
            *(uint4*)&sBhi[f][kq]      = *(const uint4*)&g_Fhi[(size_t)f * NSAMP + kc + kq];
            *(uint4*)&sBhi[f][kq + 32] = *(const uint4*)&g_Fhi[(size_t)f * NSAMP + kc + kq + 32];
            *(uint4*)&sBlo[f][kq]      = *(const uint4*)&g_Flo[(size_t)f * NSAMP + kc + kq];
            *(uint4*)&sBlo[f][kq + 32] = *(const uint4*)&g_Flo[(size_t)f * NSAMP + kc + kq + 32];
        }
        __syncthreads();
        if (ch + 1 < NCHUNK) loadA(kbase + (ch + 1) * BK);   // LDGs hidden by mma
#pragma unroll
        for (int ks = 0; ks < BK / 16; ks++) {
            wmma::fragment<wmma::matrix_a, 16, 16, 16, __nv_bfloat16, wmma::row_major> ahi, alo;
            wmma::load_matrix_sync(ahi, &sAhi[wid * 16][ks * 16], LDA);
            wmma::load_matrix_sync(alo, &sAlo[wid * 16][ks * 16], LDA);
#pragma unroll
            for (int c = 0; c < 4; c++) {
                wmma::fragment<wmma::matrix_b, 16, 16, 16, __nv_bfloat16, wmma::col_major> bhi, blo;
                wmma::load_matrix_sync(bhi, &sBhi[c * 16][ks * 16], LDA);
                wmma::load_matrix_sync(blo, &sBlo[c * 16][ks * 16], LDA);
                wmma::mma_sync(acc[c], ahi, bhi, acc[c]);
                wmma::mma_sync(acc[c], ahi, blo, acc[c]);
                wmma::mma_sync(acc[c], alo, bhi, acc[c]);
            }
        }
    }
    float* dst = &g_part[(size_t)blockIdx.y * ROWS * KDIM + (size_t)(m0 + wid * 16) * KDIM];
#pragma unroll
    for (int c = 0; c < 4; c++)
        wmma::store_matrix_sync(dst + c * 16, acc[c], KDIM, wmma::mem_row_major);
}

// ---- CFT magnitude + LayerNorm + fused slice-reduction (one blk/row) ----
__global__ void k_mag(const float* __restrict__ x,
                      const float* __restrict__ gamma,
                      const float* __restrict__ beta) {
    __shared__ float v[NNODES];
    __shared__ float pre[8][MODES], pim[8][MODES];
    __shared__ float sred[4][KDIM];
    const int row = blockIdx.x;
    const int tid = threadIdx.x;
    {
        int col = tid & 63, q = tid >> 6;
        float s0 = 0.f, s1 = 0.f;
#pragma unroll
        for (int p = 0; p < 4; p++) {
            s0 += g_part[((size_t)(q * 8 + 2 * p)     * ROWS + row) * KDIM + col];
            s1 += g_part[((size_t)(q * 8 + 2 * p + 1) * ROWS + row) * KDIM + col];
        }
        sred[q][col] = s0 + s1;
    }
    if (tid < NNODES) {
        int l = g_nodeL[tid];
        v[tid] = g_nodeWL[tid] * x[(size_t)row * NSAMP + l]
               + g_nodeWR[tid] * x[(size_t)row * NSAMP + l + 1];
    }
    __syncthreads();
    if (tid < KDIM)
        g_sfor[(size_t)row * KDIM + tid] =
            sred[0][tid] + sred[1][tid] + sred[2][tid] + sred[3][tid];
    {
        const int w = tid >> 5, f = tid & 31;
        float re = 0.0f, im = 0.0f;
        const int j0 = w * 20;
#pragma unroll
        for (int j = 0; j < 20; j++) {
            float vv = v[j0 + j];
            re = fmaf(vv, __ldg(&g_Ar[(j0 + j) * MODES + f]), re);
            im = fmaf(vv, __ldg(&g_Ai[(j0 + j) * MODES + f]), im);
        }
        pre[w][f] = re; pim[w][f] = im;
    }
    __syncthreads();
    if (tid < MODES) {
        float re = 0.0f, im = 0.0f;
#pragma unroll
        for (int w = 0; w < 8; w++) { re += pre[w][tid]; im += pim[w][tid]; }
        float mag = sqrtf(re * re + im * im);
        float mu = mag;
#pragma unroll
        for (int s = 16; s > 0; s >>= 1) mu += __shfl_xor_sync(0xffffffffu, mu, s);
        mu *= (1.0f / MODES);
        float d = mag - mu;
        float var = d * d;
#pragma unroll
        for (int s = 16; s > 0; s >>= 1) var += __shfl_xor_sync(0xffffffffu, var, s);
        var *= (1.0f / MODES);
        float inv = rsqrtf(var + 1e-5f);
        g_norm[(size_t)row * MODES + tid] = d * inv * gamma[tid] + beta[tid];
    }
}

// ---------------- 1x1 conv gate: grid (BATCH, 4) -------------------------
__global__ void k_gate(const float* __restrict__ gate_w) {
    __shared__ float sg[CH * MODES];
    const int b = blockIdx.x;
    const int o0 = blockIdx.y * 16;
    const int tid = threadIdx.x;
    for (int e = tid; e < CH * MODES; e += blockDim.x)
        sg[e] = g_norm[(size_t)b * CH * MODES + e];
    __syncthreads();
    for (int ee = tid; ee < 16 * MODES; ee += blockDim.x) {
        int o = o0 + (ee >> 5), f = ee & 31;
        float z = 0.0f;
#pragma unroll 8
        for (int i = 0; i < CH; i++)
            z = fmaf(__ldg(&gate_w[o * CH + i]), sg[i * MODES + f], z);
        g_gate[(size_t)b * CH * MODES + o * MODES + f] = 1.0f / (1.0f + expf(-z));
    }
}

// -------- per-(b, 4 freqs) 64x64 complex matvec; coef as bf16 hi/lo -------
__global__ void k_modes() {
    const int b = blockIdx.x;
    const int f0 = blockIdx.y * 4;
    const int tid = threadIdx.x;          // 256
    const int o = tid & 63, fi = tid >> 6;
    const int f = f0 + fi;
    __shared__ float gr[4][CH], gi[4][CH];
    {
        int i = o;
        float g = g_gate[((size_t)b * CH + i) * MODES + f];
        gr[fi][i] =  g_sfor[((size_t)b * CH + i) * KDIM + f] * g;
        gi[fi][i] = -g_sfor[((size_t)b * CH + i) * KDIM + MODES + f] * g;
    }
    __syncthreads();
    float orr = 0.0f, oii = 0.0f;
    const float* wr = &g_w1Tr[(size_t)f * CH * CH];
    const float* wi = &g_w1Ti[(size_t)f * CH * CH];
#pragma unroll 8
    for (int i = 0; i < CH; i++) {
        float a = gr[fi][i], c = gi[fi][i];
        float xr = wr[i * CH + o], xi = wi[i * CH + o];
        orr = fmaf(a, xr, orr); orr = fmaf(-c, xi, orr);
        oii = fmaf(a, xi, oii); oii = fmaf( c, xr, oii);
    }
    float sc = (f == 0) ? (1.0f / NSAMP) : (2.0f / NSAMP);
    int row = b * CH + o;
    float cr = sc * orr;
    float ci = (f == 0) ? 0.0f : (-sc * oii);   // imag of bin 0 ignored by hc2r
    __nv_bfloat16 h;
    h = __float2bfloat16_rn(cr);
    g_coefHi[(size_t)row * KDIM + f] = h;
    g_coefLo[(size_t)row * KDIM + f] = __float2bfloat16_rn(cr - __bfloat162float(h));
    h = __float2bfloat16_rn(ci);
    g_coefHi[(size_t)row * KDIM + MODES + f] = h;
    g_coefLo[(size_t)row * KDIM + MODES + f] = __float2bfloat16_rn(ci - __bfloat162float(h));
}

// ---------------- inverse via WMMA split-bf16, 128x128 tiles --------------
// out[2048x8192] = coef[2048x64] * F[64x8192].  grid (64, 16).
__global__ __launch_bounds__(256, 2) void k_inverse_wmma(float* __restrict__ out) {
    __shared__ __align__(32) __nv_bfloat16 sA[2][128][LDIA];  // [hi/lo][row][k] 36.9KB
    __shared__ __align__(32) __nv_bfloat16 sB[2][64][LDIB];   // [hi/lo][freq][n] 34.8KB
    const int tid = threadIdx.x, w = tid >> 5;
    const int n0 = blockIdx.x * 128;
    const int r0 = blockIdx.y * 128;
#pragma unroll
    for (int p = 0; p < 2; p++) {
        const __nv_bfloat16* src = p ? g_coefLo : g_coefHi;
#pragma unroll
        for (int q = 0; q < 4; q++) {
            int e4 = tid * 4 + q;                 // 0..1023
            int r = e4 >> 3, c = (e4 & 7) * 8;
            *(uint4*)&sA[p][r][c] = *(const uint4*)&src[(size_t)(r0 + r) * KDIM + c];
        }
    }
#pragma unroll
    for (int p = 0; p < 2; p++) {
        const __nv_bfloat16* src = p ? g_Flo : g_Fhi;
#pragma unroll
        for (int q = 0; q < 4; q++) {
            int e4 = tid * 4 + q;                 // 0..1023
            int r = e4 >> 4, c = (e4 & 15) * 8;
            *(uint4*)&sB[p][r][c] = *(const uint4*)&src[(size_t)r * NSAMP + n0 + c];
        }
    }
    __syncthreads();
    const int wm = (w & 3) * 2, wn = (w >> 2) * 4;
    wmma::fragment<wmma::accumulator, 16, 16, 16, float> acc[2][4];
#pragma unroll
    for (int i = 0; i < 2; i++)
#pragma unroll
        for (int j = 0; j < 4; j++) wmma::fill_fragment(acc[i][j], 0.0f);
#pragma unroll
    for (int kt = 0; kt < 4; kt++) {
        wmma::fragment<wmma::matrix_a, 16, 16, 16, __nv_bfloat16, wmma::row_major> ahi[2], alo[2];
#pragma unroll
        for (int i = 0; i < 2; i++) {
            wmma::load_matrix_sync(ahi[i], &sA[0][(wm + i) * 16][kt * 16], LDIA);
            wmma::load_matrix_sync(alo[i], &sA[1][(wm + i) * 16][kt * 16], LDIA);
        }
#pragma unroll
        for (int j = 0; j < 4; j++) {
            int nc = (wn + j) * 16;
            wmma::fragment<wmma::matrix_b, 16, 16, 16, __nv_bfloat16, wmma::row_major> bhi, blo;
            wmma::load_matrix_sync(bhi, &sB[0][kt * 16][nc], LDIB);
            wmma::load_matrix_sync(blo, &sB[1][kt * 16][nc], LDIB);
#pragma unroll
            for (int i = 0; i < 2; i++) {
                wmma::mma_sync(acc[i][j], ahi[i], bhi, acc[i][j]);
                wmma::mma_sync(acc[i][j], ahi[i], blo, acc[i][j]);
                wmma::mma_sync(acc[i][j], alo[i], bhi, acc[i][j]);
            }
        }
    }
#pragma unroll
    for (int i = 0; i < 2; i++)
#pragma unroll
        for (int j = 0; j < 4; j++)
            wmma::store_matrix_sync(
                &out[(size_t)(r0 + (wm + i) * 16) * NSAMP + n0 + (wn + j) * 16],
                acc[i][j], NSAMP, wmma::mem_row_major);
}

// ---------------- launch ----------------
extern "C" void kernel_launch(void* const* d_in, const int* in_sizes, int n_in,
                              void* d_out, int out_size) {
    const float* x     = (const float*)d_in[0];
    const float* w1r   = (const float*)d_in[1];
    const float* w1i   = (const float*)d_in[2];
    const float* gw    = (const float*)d_in[3];
    const float* gamma = (const float*)d_in[4];
    const float* beta  = (const float*)d_in[5];
    float* out = (float*)d_out;

    k_setup_all<<<2177, 256>>>(w1r, w1i);
    k_forward_wmma<<<dim3(ROWS / 128, KSPLIT), 256>>>(x);
    k_mag<<<ROWS, 256>>>(x, gamma, beta);
    k_gate<<<dim3(BATCH, 4), 256>>>(gw);
    k_modes<<<dim3(BATCH, MODES / 4), 256>>>();
    k_inverse_wmma<<<dim3(NSAMP / 128, ROWS / 128), 256>>>(out);
}